// round 2
// baseline (speedup 1.0000x reference)
#include <cuda_runtime.h>
#include <cuda_bf16.h>

// Problem constants
#define BB   2
#define NN_  4096
#define NQv  1024
#define DIMv 512
#define HH   8
#define DHv  64
#define LMv  256
#define BHv  16
#define INNER 512

// ---------------- scratch (device globals; no allocation allowed) ----------------
__device__ float g_kv[(long)BB*NN_*1024];      // x @ W_kv : (b,n,1024)  [k | v]
__device__ float g_qmat[(long)BB*NQv*INNER];   // (q_input @ W_q) * scale
__device__ float g_kl[BHv*LMv*DHv];            // landmarks (bh, 256, 64)
__device__ float g_attn1[(long)BHv*NQv*LMv];   // softmax(q @ kl^T) (bh,1024,256)
__device__ float g_G[BHv*LMv*LMv];             // attn1^T attn1 (bh,256,256)
__device__ float g_qA[BHv*LMv*LMv];
__device__ float g_qB[BHv*LMv*LMv];
__device__ float g_M[BHv*LMv*LMv];
__device__ float g_r1[BHv*LMv*LMv];
__device__ float g_r2[BHv*LMv*LMv];
__device__ float g_Y[BHv*NQv*DHv];             // softmax(q k^T) @ v  (bh,1024,64)
__device__ float g_xty[BHv*LMv*DHv];           // attn1^T @ Y (bh,256,64)
__device__ float g_z2[BHv*LMv*DHv];            // q6 @ xty (bh,256,64)
__device__ float g_oc[(long)BB*NQv*INNER];     // gathered output (b, i, h*64+d)
__device__ float g_max[1];

// ---------------- generic strided batched SGEMM ----------------
// C(i,j) = alpha * sum_k A(i,k)*B(k,j) + beta*D(i,j) + bias[j]
// A(i,k) = A[i*a_rs + k*a_cs]; B(k,j) = B[k*b_rs + j*b_cs]; C,D row-major ld=c_ld
// batch z = b*8+h; base offsets zb*so + zh*si per operand.
// Requires M%64==0, N%64==0, K%16==0.
__global__ __launch_bounds__(256) void sgemm_kernel(
    const float* __restrict__ A, const float* __restrict__ B,
    const float* __restrict__ D, const float* __restrict__ bias,
    float* __restrict__ C,
    int M, int N, int K,
    long sAo, long sAi, long sBo, long sBi, long sDo, long sDi, long sCo, long sCi,
    int a_rs, int a_cs, int b_rs, int b_cs, int c_ld,
    float alpha, float beta)
{
    int z = blockIdx.z; int zb = z >> 3, zh = z & 7;
    A += zb * sAo + zh * sAi;
    B += zb * sBo + zh * sBi;
    C += zb * sCo + zh * sCi;
    if (D) D += zb * sDo + zh * sDi;

    __shared__ float As[16][68];
    __shared__ float Bs[16][68];

    int tid = threadIdx.x;
    int ty = tid >> 4, tx = tid & 15;
    int i0 = blockIdx.y * 64, j0 = blockIdx.x * 64;

    float acc[4][4] = {};

    for (int k0 = 0; k0 < K; k0 += 16) {
        // ---- load A tile into As[k][i] ----
        if (a_cs == 1) {
            #pragma unroll
            for (int t = tid; t < 64 * 16; t += 256) {
                int kk = t & 15, ii = t >> 4;
                As[kk][ii] = A[(long)(i0 + ii) * a_rs + (k0 + kk)];
            }
        } else {
            #pragma unroll
            for (int t = tid; t < 64 * 16; t += 256) {
                int ii = t & 63, kk = t >> 6;
                As[kk][ii] = A[(long)(i0 + ii) * a_rs + (long)(k0 + kk) * a_cs];
            }
        }
        // ---- load B tile into Bs[k][j] ----
        if (b_cs == 1) {
            #pragma unroll
            for (int t = tid; t < 64 * 16; t += 256) {
                int jj = t & 63, kk = t >> 6;
                Bs[kk][jj] = B[(long)(k0 + kk) * b_rs + (j0 + jj)];
            }
        } else {
            #pragma unroll
            for (int t = tid; t < 64 * 16; t += 256) {
                int kk = t & 15, jj = t >> 4;
                Bs[kk][jj] = B[(long)(k0 + kk) * b_rs + (long)(j0 + jj) * b_cs];
            }
        }
        __syncthreads();

        #pragma unroll
        for (int kk = 0; kk < 16; kk++) {
            float4 av = *(const float4*)&As[kk][ty * 4];
            float4 bv = *(const float4*)&Bs[kk][tx * 4];
            float a0 = av.x, a1 = av.y, a2 = av.z, a3 = av.w;
            float b0 = bv.x, b1 = bv.y, b2 = bv.z, b3 = bv.w;
            acc[0][0] += a0 * b0; acc[0][1] += a0 * b1; acc[0][2] += a0 * b2; acc[0][3] += a0 * b3;
            acc[1][0] += a1 * b0; acc[1][1] += a1 * b1; acc[1][2] += a1 * b2; acc[1][3] += a1 * b3;
            acc[2][0] += a2 * b0; acc[2][1] += a2 * b1; acc[2][2] += a2 * b2; acc[2][3] += a2 * b3;
            acc[3][0] += a3 * b0; acc[3][1] += a3 * b1; acc[3][2] += a3 * b2; acc[3][3] += a3 * b3;
        }
        __syncthreads();
    }

    #pragma unroll
    for (int i = 0; i < 4; i++) {
        int row = i0 + ty * 4 + i;
        #pragma unroll
        for (int j = 0; j < 4; j++) {
            int col = j0 + tx * 4 + j;
            long off = (long)row * c_ld + col;
            float v = alpha * acc[i][j];
            if (D) v += beta * D[off];
            if (bias) v += bias[col];
            C[off] = v;
        }
    }
}

// ---------------- landmark pooling ----------------
// KL[bh][j][dd] = sum_{t<16} k[b,h,j*16+t,dd], k from g_kv
__global__ void landmark_kernel(const float* __restrict__ kv, float* __restrict__ kl)
{
    int dd = threadIdx.x;           // 0..63
    int j  = blockIdx.x;            // 0..255
    int bh = blockIdx.y;            // 0..15
    int b = bh >> 3, h = bh & 7;
    const float* base = kv + (long)b * NN_ * 1024 + (long)(j * 16) * 1024 + h * DHv + dd;
    float s = 0.f;
    #pragma unroll
    for (int t = 0; t < 16; t++) s += base[(long)t * 1024];
    kl[((long)bh * LMv + j) * DHv + dd] = s;
}

// ---------------- row softmax over 256 columns (in place) ----------------
__global__ void softmax256_kernel(float* __restrict__ a)
{
    int row = blockIdx.x * 8 + (threadIdx.x >> 5);
    int lane = threadIdx.x & 31;
    float* p = a + (long)row * 256;
    float v[8];
    float mx = -1e30f;
    #pragma unroll
    for (int t = 0; t < 8; t++) { v[t] = p[lane + 32 * t]; mx = fmaxf(mx, v[t]); }
    #pragma unroll
    for (int o = 16; o > 0; o >>= 1) mx = fmaxf(mx, __shfl_xor_sync(0xffffffffu, mx, o));
    float s = 0.f;
    #pragma unroll
    for (int t = 0; t < 8; t++) { v[t] = __expf(v[t] - mx); s += v[t]; }
    #pragma unroll
    for (int o = 16; o > 0; o >>= 1) s += __shfl_xor_sync(0xffffffffu, s, o);
    float inv = 1.f / s;
    #pragma unroll
    for (int t = 0; t < 8; t++) p[lane + 32 * t] = v[t] * inv;
}

// ---------------- column sums of attn1 + global max ----------------
__global__ void initmax_kernel(float* m) { m[0] = 0.f; }

__global__ void colsummax_kernel(const float* __restrict__ a, float* __restrict__ dmax)
{
    int idx = blockIdx.x * blockDim.x + threadIdx.x;    // 0..4095
    int bh = idx >> 8, j = idx & 255;
    const float* p = a + (long)bh * NQv * LMv + j;
    float s = 0.f;
    for (int i = 0; i < NQv; i++) s += p[(long)i * 256];
    atomicMax((int*)dmax, __float_as_int(s));
}

// ---------------- q0 = alpha * I ----------------
__global__ void qinit_kernel(float* __restrict__ q, const float* __restrict__ dmax)
{
    long idx = (long)blockIdx.x * 256 + threadIdx.x;    // 16*256*256
    int r = (int)((idx >> 8) & 255), c = (int)(idx & 255);
    q[idx] = (r == c) ? (1.0f / dmax[0]) : 0.f;
}

// ---------------- flash attention: Y = softmax(q k^T) @ v ----------------
// grid (NQ/64, 16), 256 threads, dynamic smem 4*64*68*4 bytes
__global__ __launch_bounds__(256) void flash_kernel(
    const float* __restrict__ qmat, const float* __restrict__ kv, float* __restrict__ Y)
{
    int bh = blockIdx.y; int b = bh >> 3, h = bh & 7;
    const float* qb = qmat + (long)b * NQv * INNER + h * DHv;   // row stride INNER
    const float* kb = kv + (long)b * NN_ * 1024 + h * DHv;      // row stride 1024
    const float* vb = kb + 512;
    int i0 = blockIdx.x * 64;

    extern __shared__ float sm[];
    float (*Qts)[68] = (float(*)[68])sm;              // [d][r]
    float (*Kts)[68] = (float(*)[68])(sm + 64 * 68);  // [d][c]
    float (*Vs)[68]  = (float(*)[68])(sm + 2 * 64 * 68); // [c][d]
    float (*Ps)[68]  = (float(*)[68])(sm + 3 * 64 * 68); // [r][c]

    int tid = threadIdx.x, ty = tid >> 4, tx = tid & 15;

    #pragma unroll
    for (int t = tid; t < 64 * 64; t += 256) {
        int r = t >> 6, dd = t & 63;
        Qts[dd][r] = qb[(long)(i0 + r) * INNER + dd];
    }

    float m[4], l[4], o[4][4];
    #pragma unroll
    for (int i = 0; i < 4; i++) { m[i] = -1e30f; l[i] = 0.f;
        #pragma unroll
        for (int j = 0; j < 4; j++) o[i][j] = 0.f; }

    for (int c0 = 0; c0 < NN_; c0 += 64) {
        #pragma unroll
        for (int t = tid; t < 64 * 64; t += 256) {
            int r = t >> 6, dd = t & 63;
            Kts[dd][r] = kb[(long)(c0 + r) * 1024 + dd];
            Vs[r][dd]  = vb[(long)(c0 + r) * 1024 + dd];
        }
        __syncthreads();

        float s[4][4] = {};
        #pragma unroll
        for (int d = 0; d < 64; d++) {
            float4 av = *(const float4*)&Qts[d][ty * 4];
            float4 bv = *(const float4*)&Kts[d][tx * 4];
            s[0][0] += av.x * bv.x; s[0][1] += av.x * bv.y; s[0][2] += av.x * bv.z; s[0][3] += av.x * bv.w;
            s[1][0] += av.y * bv.x; s[1][1] += av.y * bv.y; s[1][2] += av.y * bv.z; s[1][3] += av.y * bv.w;
            s[2][0] += av.z * bv.x; s[2][1] += av.z * bv.y; s[2][2] += av.z * bv.z; s[2][3] += av.z * bv.w;
            s[3][0] += av.w * bv.x; s[3][1] += av.w * bv.y; s[3][2] += av.w * bv.z; s[3][3] += av.w * bv.w;
        }

        #pragma unroll
        for (int i = 0; i < 4; i++) {
            float rm = fmaxf(fmaxf(s[i][0], s[i][1]), fmaxf(s[i][2], s[i][3]));
            #pragma unroll
            for (int off = 8; off > 0; off >>= 1) rm = fmaxf(rm, __shfl_xor_sync(0xffffffffu, rm, off));
            float mn = fmaxf(m[i], rm);
            float corr = __expf(m[i] - mn);
            float rs = 0.f;
            #pragma unroll
            for (int j = 0; j < 4; j++) { s[i][j] = __expf(s[i][j] - mn); rs += s[i][j]; }
            #pragma unroll
            for (int off = 8; off > 0; off >>= 1) rs += __shfl_xor_sync(0xffffffffu, rs, off);
            l[i] = l[i] * corr + rs;
            #pragma unroll
            for (int j = 0; j < 4; j++) o[i][j] *= corr;
            m[i] = mn;
            *(float4*)&Ps[ty * 4 + i][tx * 4] = make_float4(s[i][0], s[i][1], s[i][2], s[i][3]);
        }
        __syncthreads();

        #pragma unroll
        for (int c = 0; c < 64; c++) {
            float4 vv = *(const float4*)&Vs[c][tx * 4];
            float p0 = Ps[ty * 4 + 0][c], p1 = Ps[ty * 4 + 1][c];
            float p2 = Ps[ty * 4 + 2][c], p3 = Ps[ty * 4 + 3][c];
            o[0][0] += p0 * vv.x; o[0][1] += p0 * vv.y; o[0][2] += p0 * vv.z; o[0][3] += p0 * vv.w;
            o[1][0] += p1 * vv.x; o[1][1] += p1 * vv.y; o[1][2] += p1 * vv.z; o[1][3] += p1 * vv.w;
            o[2][0] += p2 * vv.x; o[2][1] += p2 * vv.y; o[2][2] += p2 * vv.z; o[2][3] += p2 * vv.w;
            o[3][0] += p3 * vv.x; o[3][1] += p3 * vv.y; o[3][2] += p3 * vv.z; o[3][3] += p3 * vv.w;
        }
        __syncthreads();
    }

    #pragma unroll
    for (int i = 0; i < 4; i++) {
        float inv = 1.f / l[i];
        #pragma unroll
        for (int j = 0; j < 4; j++)
            Y[((long)bh * NQv + (i0 + ty * 4 + i)) * DHv + tx * 4 + j] = o[i][j] * inv;
    }
}

// ---------------- host launch ----------------
static void* sym(const void* s) { void* p = nullptr; cudaGetSymbolAddress(&p, s); return p; }

extern "C" void kernel_launch(void* const* d_in, const int* in_sizes, int n_in,
                              void* d_out, int out_size)
{
    const float* x      = (const float*)d_in[0];
    const float* qin    = (const float*)d_in[1];
    const float* W_kv   = (const float*)d_in[2];
    const float* W_q    = (const float*)d_in[3];
    const float* W_out  = (const float*)d_in[4];
    const float* b_out  = (const float*)d_in[5];
    float* out = (float*)d_out;

    float* kv    = (float*)sym(g_kv);
    float* qmat  = (float*)sym(g_qmat);
    float* kl    = (float*)sym(g_kl);
    float* attn1 = (float*)sym(g_attn1);
    float* G     = (float*)sym(g_G);
    float* qA    = (float*)sym(g_qA);
    float* qB    = (float*)sym(g_qB);
    float* Mb    = (float*)sym(g_M);
    float* r1    = (float*)sym(g_r1);
    float* r2    = (float*)sym(g_r2);
    float* Yb    = (float*)sym(g_Y);
    float* xty   = (float*)sym(g_xty);
    float* z2    = (float*)sym(g_z2);
    float* oc    = (float*)sym(g_oc);
    float* dmax  = (float*)sym(g_max);

    const int FLASH_SMEM = 4 * 64 * 68 * 4;
    static bool attr_done = false;
    if (!attr_done) {
        cudaFuncSetAttribute(flash_kernel, cudaFuncAttributeMaxDynamicSharedMemorySize, FLASH_SMEM);
        attr_done = true;
    }

    const float scale = 0.125f;    // 64^-0.5
    const long PQ = (long)LMv * LMv;         // 65536
    const long A1 = (long)NQv * LMv;         // 262144

    // 1) kv = x @ W_kv   (8192 x 1024 x 512)
    sgemm_kernel<<<dim3(1024/64, 8192/64, 1), 256>>>(
        x, W_kv, nullptr, nullptr, kv, 8192, 1024, 512,
        0,0, 0,0, 0,0, 0,0, 512,1, 1024,1, 1024, 1.f, 0.f);

    // 2) qmat = scale * (q_input @ W_q)  (2048 x 512 x 512)
    sgemm_kernel<<<dim3(512/64, 2048/64, 1), 256>>>(
        qin, W_q, nullptr, nullptr, qmat, 2048, 512, 512,
        0,0, 0,0, 0,0, 0,0, 512,1, 512,1, 512, scale, 0.f);

    // 3) landmarks
    landmark_kernel<<<dim3(256, 16), 64>>>(kv, kl);

    // 4) sim1 = q @ kl^T per bh (1024 x 256 x 64)
    sgemm_kernel<<<dim3(256/64, 1024/64, 16), 256>>>(
        qmat, kl, nullptr, nullptr, attn1, 1024, 256, 64,
        (long)NQv*INNER, 64,  8*(long)LMv*DHv, (long)LMv*DHv,  0,0,  8*A1, A1,
        512,1, 1,64, 256, 1.f, 0.f);

    // 5) softmax rows (in place) -> attn1
    softmax256_kernel<<<(BHv * NQv) / 8, 256>>>(attn1);

    // 6) G = attn1^T attn1 per bh (256 x 256 x 1024)
    sgemm_kernel<<<dim3(4, 4, 16), 256>>>(
        attn1, attn1, nullptr, nullptr, G, 256, 256, 1024,
        8*A1, A1, 8*A1, A1, 0,0, 8*PQ, PQ,
        1,256, 256,1, 256, 1.f, 0.f);

    // 7) alpha = 1 / max_j sum_i attn1[i,j]
    initmax_kernel<<<1, 1>>>(dmax);
    colsummax_kernel<<<16, 256>>>(attn1, dmax);
    qinit_kernel<<<(BHv * 256 * 256) / 256, 256>>>(qA, dmax);

    // 8) 6 pinv iterations in Gram space (all 256x256x256, batch 16)
    float* qc = qA; float* qn = qB;
    for (int it = 0; it < 6; it++) {
        // M = q @ G
        sgemm_kernel<<<dim3(4, 4, 16), 256>>>(
            qc, G, nullptr, nullptr, Mb, 256, 256, 256,
            8*PQ, PQ, 8*PQ, PQ, 0,0, 8*PQ, PQ, 256,1, 256,1, 256, 1.f, 0.f);
        // r1 = 7q - M@q
        sgemm_kernel<<<dim3(4, 4, 16), 256>>>(
            Mb, qc, qc, nullptr, r1, 256, 256, 256,
            8*PQ, PQ, 8*PQ, PQ, 8*PQ, PQ, 8*PQ, PQ, 256,1, 256,1, 256, -1.f, 7.f);
        // r2 = 15q - M@r1
        sgemm_kernel<<<dim3(4, 4, 16), 256>>>(
            Mb, r1, qc, nullptr, r2, 256, 256, 256,
            8*PQ, PQ, 8*PQ, PQ, 8*PQ, PQ, 8*PQ, PQ, 256,1, 256,1, 256, -1.f, 15.f);
        // qn = 3.25q - 0.25*M@r2
        sgemm_kernel<<<dim3(4, 4, 16), 256>>>(
            Mb, r2, qc, nullptr, qn, 256, 256, 256,
            8*PQ, PQ, 8*PQ, PQ, 8*PQ, PQ, 8*PQ, PQ, 256,1, 256,1, 256, -0.25f, 3.25f);
        float* t = qc; qc = qn; qn = t;
    }
    // final q in qc

    // 9) Y = softmax(q k^T) @ v  (flash)
    flash_kernel<<<dim3(NQv / 64, 16), 256, FLASH_SMEM>>>(qmat, kv, Yb);

    // 10) xty = attn1^T @ Y per bh (256 x 64 x 1024)
    sgemm_kernel<<<dim3(1, 4, 16), 256>>>(
        attn1, Yb, nullptr, nullptr, xty, 256, 64, 1024,
        8*A1, A1, 8*(long)NQv*DHv, (long)NQv*DHv, 0,0, 8*(long)LMv*DHv, (long)LMv*DHv,
        1,256, 64,1, 64, 1.f, 0.f);

    // 11) z2 = q6 @ xty per bh (256 x 64 x 256)
    sgemm_kernel<<<dim3(1, 4, 16), 256>>>(
        qc, xty, nullptr, nullptr, z2, 256, 64, 256,
        8*PQ, PQ, 8*(long)LMv*DHv, (long)LMv*DHv, 0,0, 8*(long)LMv*DHv, (long)LMv*DHv,
        256,1, 64,1, 64, 1.f, 0.f);

    // 12) O = attn1 @ z2 per bh -> gather into oc[b][i][h*64+dd]  (1024 x 64 x 256)
    sgemm_kernel<<<dim3(1, 16, 16), 256>>>(
        attn1, z2, nullptr, nullptr, oc, 1024, 64, 256,
        8*A1, A1, 8*(long)LMv*DHv, (long)LMv*DHv, 0,0, (long)NQv*INNER, 64,
        256,1, 64,1, 512, 1.f, 0.f);

    // 13) out = oc @ W_out + b_out (2048 x 512 x 512)
    sgemm_kernel<<<dim3(512/64, 2048/64, 1), 256>>>(
        oc, W_out, nullptr, b_out, out, 2048, 512, 512,
        0,0, 0,0, 0,0, 0,0, 512,1, 512,1, 512, 1.f, 0.f);
}

// round 3
// speedup vs baseline: 1.2269x; 1.2269x over previous
#include <cuda_runtime.h>
#include <cuda_bf16.h>

// Problem constants
#define BB   2
#define NN_  4096
#define NQv  1024
#define DIMv 512
#define HH   8
#define DHv  64
#define LMv  256
#define BHv  16
#define INNER 512

// ---------------- scratch (device globals; no allocation allowed) ----------------
__device__ float g_kv[(long)BB*NN_*1024];      // x @ W_kv : (b,n,1024)  [k | v]
__device__ float g_qmat[(long)BB*NQv*INNER];   // (q_input @ W_q) * scale
__device__ float g_kl[BHv*LMv*DHv];            // landmarks (bh, 256, 64)
__device__ float g_attn1[(long)BHv*NQv*LMv];   // softmax(q @ kl^T) (bh,1024,256)
__device__ float g_G[BHv*LMv*LMv];             // attn1^T attn1 (bh,256,256)
__device__ float g_qA[BHv*LMv*LMv];
__device__ float g_qB[BHv*LMv*LMv];
__device__ float g_M[BHv*LMv*LMv];
__device__ float g_r1[BHv*LMv*LMv];
__device__ float g_r2[BHv*LMv*LMv];
__device__ float g_Y[BHv*NQv*DHv];             // softmax(q k^T) @ v  (bh,1024,64)
__device__ float g_xty[BHv*LMv*DHv];           // attn1^T @ Y (bh,256,64)
__device__ float g_z2[BHv*LMv*DHv];            // q6 @ xty (bh,256,64)
__device__ float g_oc[(long)BB*NQv*INNER];     // gathered output (b, i, h*64+d)
__device__ float g_max[1];

// ---------------- high-throughput 128x128 SGEMM (contiguous row-major A,B,C) ------
// C = alpha * A@B (+ bias[col]).  A: MxK ld=K, B: KxN ld=N, C: MxN ld=N.
// 256 threads, 8x8 per thread, K-chunk 8, double-buffered smem, 1 sync/chunk.
// Requires M%128==0, N%128==0, K%8==0.
__global__ __launch_bounds__(256) void sgemm128_kernel(
    const float* __restrict__ A, const float* __restrict__ B,
    const float* __restrict__ bias, float* __restrict__ C,
    int M, int N, int K, float alpha)
{
    __shared__ float As[2][8][132];
    __shared__ float Bs[2][8][128];

    int tid = threadIdx.x;
    int ty = tid >> 4, tx = tid & 15;
    int i0 = blockIdx.y * 128, j0 = blockIdx.x * 128;

    int arow = tid >> 1, akq = (tid & 1) * 4;     // A: 128 rows x 8 k, 1 float4/thread
    int bkr = tid >> 5, bcq = (tid & 31) * 4;     // B: 8 k x 128 cols, 1 float4/thread

    const float* Aptr = A + (long)(i0 + arow) * K + akq;
    const float* Bptr = B + (long)bkr * N + j0 + bcq;

    float4 av = *(const float4*)Aptr;
    float4 bv = *(const float4*)Bptr;
    As[0][akq + 0][arow] = av.x; As[0][akq + 1][arow] = av.y;
    As[0][akq + 2][arow] = av.z; As[0][akq + 3][arow] = av.w;
    *(float4*)&Bs[0][bkr][bcq] = bv;
    __syncthreads();

    float acc[8][8] = {};
    int T = K / 8;
    int buf = 0;
    for (int t = 0; t < T; t++) {
        if (t + 1 < T) {
            av = *(const float4*)(Aptr + (t + 1) * 8);
            bv = *(const float4*)(Bptr + (long)(t + 1) * 8 * N);
        }
        #pragma unroll
        for (int kk = 0; kk < 8; kk++) {
            float4 a0 = *(const float4*)&As[buf][kk][ty * 8];
            float4 a1 = *(const float4*)&As[buf][kk][ty * 8 + 4];
            float4 b0 = *(const float4*)&Bs[buf][kk][tx * 8];
            float4 b1 = *(const float4*)&Bs[buf][kk][tx * 8 + 4];
            float ar[8] = {a0.x, a0.y, a0.z, a0.w, a1.x, a1.y, a1.z, a1.w};
            float br[8] = {b0.x, b0.y, b0.z, b0.w, b1.x, b1.y, b1.z, b1.w};
            #pragma unroll
            for (int i = 0; i < 8; i++)
                #pragma unroll
                for (int j = 0; j < 8; j++)
                    acc[i][j] += ar[i] * br[j];
        }
        if (t + 1 < T) {
            int nb = buf ^ 1;
            As[nb][akq + 0][arow] = av.x; As[nb][akq + 1][arow] = av.y;
            As[nb][akq + 2][arow] = av.z; As[nb][akq + 3][arow] = av.w;
            *(float4*)&Bs[nb][bkr][bcq] = bv;
            __syncthreads();
            buf = nb;
        }
    }

    #pragma unroll
    for (int i = 0; i < 8; i++) {
        long row = i0 + ty * 8 + i;
        #pragma unroll
        for (int jq = 0; jq < 2; jq++) {
            int col = j0 + tx * 8 + jq * 4;
            float4 v;
            v.x = alpha * acc[i][jq * 4 + 0];
            v.y = alpha * acc[i][jq * 4 + 1];
            v.z = alpha * acc[i][jq * 4 + 2];
            v.w = alpha * acc[i][jq * 4 + 3];
            if (bias) {
                v.x += bias[col + 0]; v.y += bias[col + 1];
                v.z += bias[col + 2]; v.w += bias[col + 3];
            }
            *(float4*)&C[row * N + col] = v;
        }
    }
}

// ---------------- generic strided batched SGEMM (64x64 tiles) ----------------
// C(i,j) = alpha * sum_k A(i,k)*B(k,j) + beta*D(i,j) + bias[j]
__global__ __launch_bounds__(256) void sgemm_kernel(
    const float* __restrict__ A, const float* __restrict__ B,
    const float* __restrict__ D, const float* __restrict__ bias,
    float* __restrict__ C,
    int M, int N, int K,
    long sAo, long sAi, long sBo, long sBi, long sDo, long sDi, long sCo, long sCi,
    int a_rs, int a_cs, int b_rs, int b_cs, int c_ld,
    float alpha, float beta)
{
    int z = blockIdx.z; int zb = z >> 3, zh = z & 7;
    A += zb * sAo + zh * sAi;
    B += zb * sBo + zh * sBi;
    C += zb * sCo + zh * sCi;
    if (D) D += zb * sDo + zh * sDi;

    __shared__ float As[16][68];
    __shared__ float Bs[16][68];

    int tid = threadIdx.x;
    int ty = tid >> 4, tx = tid & 15;
    int i0 = blockIdx.y * 64, j0 = blockIdx.x * 64;

    float acc[4][4] = {};

    for (int k0 = 0; k0 < K; k0 += 16) {
        if (a_cs == 1) {
            #pragma unroll
            for (int t = tid; t < 64 * 16; t += 256) {
                int kk = t & 15, ii = t >> 4;
                As[kk][ii] = A[(long)(i0 + ii) * a_rs + (k0 + kk)];
            }
        } else {
            #pragma unroll
            for (int t = tid; t < 64 * 16; t += 256) {
                int ii = t & 63, kk = t >> 6;
                As[kk][ii] = A[(long)(i0 + ii) * a_rs + (long)(k0 + kk) * a_cs];
            }
        }
        if (b_cs == 1) {
            #pragma unroll
            for (int t = tid; t < 64 * 16; t += 256) {
                int jj = t & 63, kk = t >> 6;
                Bs[kk][jj] = B[(long)(k0 + kk) * b_rs + (j0 + jj)];
            }
        } else {
            #pragma unroll
            for (int t = tid; t < 64 * 16; t += 256) {
                int kk = t & 15, jj = t >> 4;
                Bs[kk][jj] = B[(long)(k0 + kk) * b_rs + (long)(j0 + jj) * b_cs];
            }
        }
        __syncthreads();

        #pragma unroll
        for (int kk = 0; kk < 16; kk++) {
            float4 av = *(const float4*)&As[kk][ty * 4];
            float4 bv = *(const float4*)&Bs[kk][tx * 4];
            float a0 = av.x, a1 = av.y, a2 = av.z, a3 = av.w;
            float b0 = bv.x, b1 = bv.y, b2 = bv.z, b3 = bv.w;
            acc[0][0] += a0 * b0; acc[0][1] += a0 * b1; acc[0][2] += a0 * b2; acc[0][3] += a0 * b3;
            acc[1][0] += a1 * b0; acc[1][1] += a1 * b1; acc[1][2] += a1 * b2; acc[1][3] += a1 * b3;
            acc[2][0] += a2 * b0; acc[2][1] += a2 * b1; acc[2][2] += a2 * b2; acc[2][3] += a2 * b3;
            acc[3][0] += a3 * b0; acc[3][1] += a3 * b1; acc[3][2] += a3 * b2; acc[3][3] += a3 * b3;
        }
        __syncthreads();
    }

    #pragma unroll
    for (int i = 0; i < 4; i++) {
        int row = i0 + ty * 4 + i;
        #pragma unroll
        for (int j = 0; j < 4; j++) {
            int col = j0 + tx * 4 + j;
            long off = (long)row * c_ld + col;
            float v = alpha * acc[i][j];
            if (D) v += beta * D[off];
            if (bias) v += bias[col];
            C[off] = v;
        }
    }
}

// ---------------- landmark pooling ----------------
__global__ void landmark_kernel(const float* __restrict__ kv, float* __restrict__ kl)
{
    int dd = threadIdx.x;           // 0..63
    int j  = blockIdx.x;            // 0..255
    int bh = blockIdx.y;            // 0..15
    int b = bh >> 3, h = bh & 7;
    const float* base = kv + (long)b * NN_ * 1024 + (long)(j * 16) * 1024 + h * DHv + dd;
    float s = 0.f;
    #pragma unroll
    for (int t = 0; t < 16; t++) s += base[(long)t * 1024];
    kl[((long)bh * LMv + j) * DHv + dd] = s;
}

// ---------------- row softmax over 256 columns (in place) ----------------
__global__ void softmax256_kernel(float* __restrict__ a)
{
    int row = blockIdx.x * 8 + (threadIdx.x >> 5);
    int lane = threadIdx.x & 31;
    float* p = a + (long)row * 256;
    float v[8];
    float mx = -1e30f;
    #pragma unroll
    for (int t = 0; t < 8; t++) { v[t] = p[lane + 32 * t]; mx = fmaxf(mx, v[t]); }
    #pragma unroll
    for (int o = 16; o > 0; o >>= 1) mx = fmaxf(mx, __shfl_xor_sync(0xffffffffu, mx, o));
    float s = 0.f;
    #pragma unroll
    for (int t = 0; t < 8; t++) { v[t] = __expf(v[t] - mx); s += v[t]; }
    #pragma unroll
    for (int o = 16; o > 0; o >>= 1) s += __shfl_xor_sync(0xffffffffu, s, o);
    float inv = 1.f / s;
    #pragma unroll
    for (int t = 0; t < 8; t++) p[lane + 32 * t] = v[t] * inv;
}

// ---------------- column sums of attn1 + global max ----------------
__global__ void initmax_kernel(float* m) { m[0] = 0.f; }

__global__ void colsummax_kernel(const float* __restrict__ a, float* __restrict__ dmax)
{
    int idx = blockIdx.x * blockDim.x + threadIdx.x;    // 0..4095
    int bh = idx >> 8, j = idx & 255;
    const float* p = a + (long)bh * NQv * LMv + j;
    float s = 0.f;
    for (int i = 0; i < NQv; i++) s += p[(long)i * 256];
    atomicMax((int*)dmax, __float_as_int(s));
}

// ---------------- q0 = alpha * I ----------------
__global__ void qinit_kernel(float* __restrict__ q, const float* __restrict__ dmax)
{
    long idx = (long)blockIdx.x * 256 + threadIdx.x;    // 16*256*256
    int r = (int)((idx >> 8) & 255), c = (int)(idx & 255);
    q[idx] = (r == c) ? (1.0f / dmax[0]) : 0.f;
}

// ---------------- flash attention: Y = softmax(q k^T) @ v ----------------
__global__ __launch_bounds__(256) void flash_kernel(
    const float* __restrict__ qmat, const float* __restrict__ kv, float* __restrict__ Y)
{
    int bh = blockIdx.y; int b = bh >> 3, h = bh & 7;
    const float* qb = qmat + (long)b * NQv * INNER + h * DHv;   // row stride INNER
    const float* kb = kv + (long)b * NN_ * 1024 + h * DHv;      // row stride 1024
    const float* vb = kb + 512;
    int i0 = blockIdx.x * 64;

    extern __shared__ float sm[];
    float (*Qts)[68] = (float(*)[68])sm;              // [d][r]
    float (*Kts)[68] = (float(*)[68])(sm + 64 * 68);  // [d][c]
    float (*Vs)[68]  = (float(*)[68])(sm + 2 * 64 * 68); // [c][d]
    float (*Ps)[68]  = (float(*)[68])(sm + 3 * 64 * 68); // [r][c]

    int tid = threadIdx.x, ty = tid >> 4, tx = tid & 15;

    #pragma unroll
    for (int t = tid; t < 64 * 64; t += 256) {
        int r = t >> 6, dd = t & 63;
        Qts[dd][r] = qb[(long)(i0 + r) * INNER + dd];
    }

    float m[4], l[4], o[4][4];
    #pragma unroll
    for (int i = 0; i < 4; i++) { m[i] = -1e30f; l[i] = 0.f;
        #pragma unroll
        for (int j = 0; j < 4; j++) o[i][j] = 0.f; }

    for (int c0 = 0; c0 < NN_; c0 += 64) {
        #pragma unroll
        for (int t = tid; t < 64 * 64; t += 256) {
            int r = t >> 6, dd = t & 63;
            Kts[dd][r] = kb[(long)(c0 + r) * 1024 + dd];
            Vs[r][dd]  = vb[(long)(c0 + r) * 1024 + dd];
        }
        __syncthreads();

        float s[4][4] = {};
        #pragma unroll
        for (int d = 0; d < 64; d++) {
            float4 av = *(const float4*)&Qts[d][ty * 4];
            float4 bv = *(const float4*)&Kts[d][tx * 4];
            s[0][0] += av.x * bv.x; s[0][1] += av.x * bv.y; s[0][2] += av.x * bv.z; s[0][3] += av.x * bv.w;
            s[1][0] += av.y * bv.x; s[1][1] += av.y * bv.y; s[1][2] += av.y * bv.z; s[1][3] += av.y * bv.w;
            s[2][0] += av.z * bv.x; s[2][1] += av.z * bv.y; s[2][2] += av.z * bv.z; s[2][3] += av.z * bv.w;
            s[3][0] += av.w * bv.x; s[3][1] += av.w * bv.y; s[3][2] += av.w * bv.z; s[3][3] += av.w * bv.w;
        }

        #pragma unroll
        for (int i = 0; i < 4; i++) {
            float rm = fmaxf(fmaxf(s[i][0], s[i][1]), fmaxf(s[i][2], s[i][3]));
            #pragma unroll
            for (int off = 8; off > 0; off >>= 1) rm = fmaxf(rm, __shfl_xor_sync(0xffffffffu, rm, off));
            float mn = fmaxf(m[i], rm);
            float corr = __expf(m[i] - mn);
            float rs = 0.f;
            #pragma unroll
            for (int j = 0; j < 4; j++) { s[i][j] = __expf(s[i][j] - mn); rs += s[i][j]; }
            #pragma unroll
            for (int off = 8; off > 0; off >>= 1) rs += __shfl_xor_sync(0xffffffffu, rs, off);
            l[i] = l[i] * corr + rs;
            #pragma unroll
            for (int j = 0; j < 4; j++) o[i][j] *= corr;
            m[i] = mn;
            *(float4*)&Ps[ty * 4 + i][tx * 4] = make_float4(s[i][0], s[i][1], s[i][2], s[i][3]);
        }
        __syncthreads();

        #pragma unroll
        for (int c = 0; c < 64; c++) {
            float4 vv = *(const float4*)&Vs[c][tx * 4];
            float p0 = Ps[ty * 4 + 0][c], p1 = Ps[ty * 4 + 1][c];
            float p2 = Ps[ty * 4 + 2][c], p3 = Ps[ty * 4 + 3][c];
            o[0][0] += p0 * vv.x; o[0][1] += p0 * vv.y; o[0][2] += p0 * vv.z; o[0][3] += p0 * vv.w;
            o[1][0] += p1 * vv.x; o[1][1] += p1 * vv.y; o[1][2] += p1 * vv.z; o[1][3] += p1 * vv.w;
            o[2][0] += p2 * vv.x; o[2][1] += p2 * vv.y; o[2][2] += p2 * vv.z; o[2][3] += p2 * vv.w;
            o[3][0] += p3 * vv.x; o[3][1] += p3 * vv.y; o[3][2] += p3 * vv.z; o[3][3] += p3 * vv.w;
        }
        __syncthreads();
    }

    #pragma unroll
    for (int i = 0; i < 4; i++) {
        float inv = 1.f / l[i];
        #pragma unroll
        for (int j = 0; j < 4; j++)
            Y[((long)bh * NQv + (i0 + ty * 4 + i)) * DHv + tx * 4 + j] = o[i][j] * inv;
    }
}

// ---------------- host launch ----------------
static void* sym(const void* s) { void* p = nullptr; cudaGetSymbolAddress(&p, s); return p; }

extern "C" void kernel_launch(void* const* d_in, const int* in_sizes, int n_in,
                              void* d_out, int out_size)
{
    const float* x      = (const float*)d_in[0];
    const float* qin    = (const float*)d_in[1];
    const float* W_kv   = (const float*)d_in[2];
    const float* W_q    = (const float*)d_in[3];
    const float* W_out  = (const float*)d_in[4];
    const float* b_out  = (const float*)d_in[5];
    float* out = (float*)d_out;

    float* kv    = (float*)sym(g_kv);
    float* qmat  = (float*)sym(g_qmat);
    float* kl    = (float*)sym(g_kl);
    float* attn1 = (float*)sym(g_attn1);
    float* G     = (float*)sym(g_G);
    float* qA    = (float*)sym(g_qA);
    float* qB    = (float*)sym(g_qB);
    float* Mb    = (float*)sym(g_M);
    float* r1    = (float*)sym(g_r1);
    float* r2    = (float*)sym(g_r2);
    float* Yb    = (float*)sym(g_Y);
    float* xty   = (float*)sym(g_xty);
    float* z2    = (float*)sym(g_z2);
    float* oc    = (float*)sym(g_oc);
    float* dmax  = (float*)sym(g_max);

    const int FLASH_SMEM = 4 * 64 * 68 * 4;

    // one-time init (first call is the uncaptured correctness run)
    static bool init_done = false;
    static cudaStream_t s1;
    static cudaEvent_t eIn, eKV, eQ, eAttn, eY;
    if (!init_done) {
        cudaFuncSetAttribute(flash_kernel, cudaFuncAttributeMaxDynamicSharedMemorySize, FLASH_SMEM);
        cudaStreamCreateWithFlags(&s1, cudaStreamNonBlocking);
        cudaEventCreateWithFlags(&eIn,   cudaEventDisableTiming);
        cudaEventCreateWithFlags(&eKV,   cudaEventDisableTiming);
        cudaEventCreateWithFlags(&eQ,    cudaEventDisableTiming);
        cudaEventCreateWithFlags(&eAttn, cudaEventDisableTiming);
        cudaEventCreateWithFlags(&eY,    cudaEventDisableTiming);
        init_done = true;
    }

    const float scale = 0.125f;    // 64^-0.5
    const long PQ = (long)LMv * LMv;         // 65536
    const long A1 = (long)NQv * LMv;         // 262144

    // fork point
    cudaEventRecord(eIn, 0);
    cudaStreamWaitEvent(s1, eIn, 0);

    // s0: kv = x @ W_kv   (8192 x 1024 x 512)
    sgemm128_kernel<<<dim3(1024/128, 8192/128, 1), 256, 0, 0>>>(
        x, W_kv, nullptr, kv, 8192, 1024, 512, 1.f);

    // s1: qmat = scale * (q_input @ W_q)  (2048 x 512 x 512)
    sgemm128_kernel<<<dim3(512/128, 2048/128, 1), 256, 0, s1>>>(
        qin, W_q, nullptr, qmat, 2048, 512, 512, scale);
    cudaEventRecord(eQ, s1);

    // s0: landmarks (needs kv)
    landmark_kernel<<<dim3(256, 16), 64, 0, 0>>>(kv, kl);
    cudaEventRecord(eKV, 0);     // kv (and landmarks) ready

    // s0: sim1 = q @ kl^T per bh (needs qmat)
    cudaStreamWaitEvent(0, eQ, 0);
    sgemm_kernel<<<dim3(256/64, 1024/64, 16), 256, 0, 0>>>(
        qmat, kl, nullptr, nullptr, attn1, 1024, 256, 64,
        (long)NQv*INNER, 64,  8*(long)LMv*DHv, (long)LMv*DHv,  0,0,  8*A1, A1,
        512,1, 1,64, 256, 1.f, 0.f);

    // s0: softmax rows (in place) -> attn1
    softmax256_kernel<<<(BHv * NQv) / 8, 256, 0, 0>>>(attn1);
    cudaEventRecord(eAttn, 0);

    // ---- s1 branch: flash (needs kv+qmat), then xty (needs attn1+Y) ----
    cudaStreamWaitEvent(s1, eKV, 0);
    flash_kernel<<<dim3(NQv / 64, 16), 256, FLASH_SMEM, s1>>>(qmat, kv, Yb);
    cudaStreamWaitEvent(s1, eAttn, 0);
    // xty = attn1^T @ Y per bh (256 x 64 x 1024)
    sgemm_kernel<<<dim3(1, 4, 16), 256, 0, s1>>>(
        attn1, Yb, nullptr, nullptr, xty, 256, 64, 1024,
        8*A1, A1, 8*(long)NQv*DHv, (long)NQv*DHv, 0,0, 8*(long)LMv*DHv, (long)LMv*DHv,
        1,256, 64,1, 64, 1.f, 0.f);
    cudaEventRecord(eY, s1);

    // ---- s0 branch: G + alpha + pinv chain ----
    // G = attn1^T attn1 per bh (256 x 256 x 1024)
    sgemm_kernel<<<dim3(4, 4, 16), 256, 0, 0>>>(
        attn1, attn1, nullptr, nullptr, G, 256, 256, 1024,
        8*A1, A1, 8*A1, A1, 0,0, 8*PQ, PQ,
        1,256, 256,1, 256, 1.f, 0.f);

    initmax_kernel<<<1, 1, 0, 0>>>(dmax);
    colsummax_kernel<<<16, 256, 0, 0>>>(attn1, dmax);
    qinit_kernel<<<(BHv * 256 * 256) / 256, 256, 0, 0>>>(qA, dmax);

    // 6 pinv iterations in Gram space (all 256x256x256, batch 16)
    float* qc = qA; float* qn = qB;
    for (int it = 0; it < 6; it++) {
        // M = q @ G
        sgemm_kernel<<<dim3(4, 4, 16), 256, 0, 0>>>(
            qc, G, nullptr, nullptr, Mb, 256, 256, 256,
            8*PQ, PQ, 8*PQ, PQ, 0,0, 8*PQ, PQ, 256,1, 256,1, 256, 1.f, 0.f);
        // r1 = 7q - M@q
        sgemm_kernel<<<dim3(4, 4, 16), 256, 0, 0>>>(
            Mb, qc, qc, nullptr, r1, 256, 256, 256,
            8*PQ, PQ, 8*PQ, PQ, 8*PQ, PQ, 8*PQ, PQ, 256,1, 256,1, 256, -1.f, 7.f);
        // r2 = 15q - M@r1
        sgemm_kernel<<<dim3(4, 4, 16), 256, 0, 0>>>(
            Mb, r1, qc, nullptr, r2, 256, 256, 256,
            8*PQ, PQ, 8*PQ, PQ, 8*PQ, PQ, 8*PQ, PQ, 256,1, 256,1, 256, -1.f, 15.f);
        // qn = 3.25q - 0.25*M@r2
        sgemm_kernel<<<dim3(4, 4, 16), 256, 0, 0>>>(
            Mb, r2, qc, nullptr, qn, 256, 256, 256,
            8*PQ, PQ, 8*PQ, PQ, 8*PQ, PQ, 8*PQ, PQ, 256,1, 256,1, 256, -0.25f, 3.25f);
        float* t = qc; qc = qn; qn = t;
    }
    // final q in qc

    // join: z2 needs q6 (s0) and xty (s1)
    cudaStreamWaitEvent(0, eY, 0);

    // z2 = q6 @ xty per bh (256 x 64 x 256)
    sgemm_kernel<<<dim3(1, 4, 16), 256, 0, 0>>>(
        qc, xty, nullptr, nullptr, z2, 256, 64, 256,
        8*PQ, PQ, 8*(long)LMv*DHv, (long)LMv*DHv, 0,0, 8*(long)LMv*DHv, (long)LMv*DHv,
        256,1, 64,1, 64, 1.f, 0.f);

    // O = attn1 @ z2 per bh -> gather into oc[b][i][h*64+dd]  (1024 x 64 x 256)
    sgemm_kernel<<<dim3(1, 16, 16), 256, 0, 0>>>(
        attn1, z2, nullptr, nullptr, oc, 1024, 64, 256,
        8*A1, A1, 8*(long)LMv*DHv, (long)LMv*DHv, 0,0, (long)NQv*INNER, 64,
        256,1, 64,1, 512, 1.f, 0.f);

    // out = oc @ W_out + b_out (2048 x 512 x 512)
    sgemm128_kernel<<<dim3(512/128, 2048/128, 1), 256, 0, 0>>>(
        oc, W_out, b_out, out, 2048, 512, 512, 1.f);
}